// round 1
// baseline (speedup 1.0000x reference)
#include <cuda_runtime.h>
#include <cuda_bf16.h>
#include <cstdint>

// Embedding gather + sinusoidal positional encoding.
// out[row, c] = W[ids[row], c] + (row even ? sin : cos)(row / 10000^(2c/D))
//
// D = 1024, TOKENS = 8192. One block per row, 256 threads, float4 per thread.

static constexpr int D = 1024;
static constexpr int VEC = 4;
static constexpr int THREADS = D / VEC;  // 256

__global__ __launch_bounds__(THREADS)
void emb_pe_kernel(const int* __restrict__ ids,
                   const float* __restrict__ W,
                   float* __restrict__ out)
{
    const int row = blockIdx.x;
    const int t   = threadIdx.x;           // 0..255
    const int c0  = t * VEC;                // starting column

    const int idx = __ldg(ids + row);       // broadcast across block

    const float4 v = *reinterpret_cast<const float4*>(W + (size_t)idx * D + c0);

    // freq_c = 10000^(-2c/D) = 2^(-log2(10000) * 2c / D)
    // log2(10000) = 13.287712379549449
    const float kexp = -13.287712379549449f * 2.0f / (float)D;
    const float pos  = (float)row;
    const bool  even = (row & 1) == 0;

    float pe[VEC];
#pragma unroll
    for (int i = 0; i < VEC; i++) {
        float freq  = exp2f(kexp * (float)(c0 + i));
        float angle = pos * freq;
        pe[i] = even ? sinf(angle) : cosf(angle);
    }

    float4 r;
    r.x = v.x + pe[0];
    r.y = v.y + pe[1];
    r.z = v.z + pe[2];
    r.w = v.w + pe[3];

    *reinterpret_cast<float4*>(out + (size_t)row * D + c0) = r;
}

extern "C" void kernel_launch(void* const* d_in, const int* in_sizes, int n_in,
                              void* d_out, int out_size)
{
    const int*   ids = (const int*)d_in[0];
    const float* W   = (const float*)d_in[1];
    float*       out = (float*)d_out;

    const int rows = in_sizes[0];           // 8192 tokens
    emb_pe_kernel<<<rows, THREADS>>>(ids, W, out);
}

// round 2
// speedup vs baseline: 1.3145x; 1.3145x over previous
#include <cuda_runtime.h>
#include <cuda_bf16.h>
#include <cstdint>

// Embedding gather + sinusoidal positional encoding.
// out[row, c] = W[ids[row], c] + (row even ? sin : cos)(row * freq(c)),
//   freq(c) = 10000^(-2c/D)
//
// D = 1024, TOKENS = 8192.
// Block = 16 rows x 1024 cols. Thread t owns columns 4t..4t+3 for all 16 rows.
// PE computed by angle recurrence: accurate sincosf once per column for the
// start angle and the per-row delta, then a 4-FMA rotation per column per row.

static constexpr int D       = 1024;
static constexpr int VEC     = 4;
static constexpr int THREADS = D / VEC;   // 256
static constexpr int R       = 16;        // rows per block (even!)

__global__ __launch_bounds__(THREADS)
void emb_pe_kernel(const int* __restrict__ ids,
                   const float* __restrict__ W,
                   float* __restrict__ out)
{
    const int row0 = blockIdx.x * R;          // always even
    const int t    = threadIdx.x;             // 0..255
    const int c0   = t * VEC;                 // starting column

    __shared__ int sids[R];
    if (t < R) sids[t] = ids[row0 + t];
    __syncthreads();

    // freq(c) = 2^(kexp * c),  kexp = -2*log2(10000)/D
    const float kexp = -13.287712379549449f * 2.0f / (float)D;
    const float pos0 = (float)row0;

    float s[VEC], c[VEC], sd[VEC], cd[VEC];
#pragma unroll
    for (int i = 0; i < VEC; i++) {
        float freq = exp2f(kexp * (float)(c0 + i));
        sincosf(pos0 * freq, &s[i], &c[i]);   // start rotor (accurate)
        sincosf(freq,        &sd[i], &cd[i]); // per-row delta rotor
    }

    const float* Wc   = W   + c0;
    float*       outp = out + (size_t)row0 * D + c0;

#pragma unroll 4
    for (int r = 0; r < R; r += 2) {
        const float4 v0 = *reinterpret_cast<const float4*>(Wc + (size_t)sids[r]     * D);
        const float4 v1 = *reinterpret_cast<const float4*>(Wc + (size_t)sids[r + 1] * D);

        // even row: add sin
        float4 o0;
        o0.x = v0.x + s[0];
        o0.y = v0.y + s[1];
        o0.z = v0.z + s[2];
        o0.w = v0.w + s[3];
        *reinterpret_cast<float4*>(outp + (size_t)r * D) = o0;

        // rotate to row r+1
#pragma unroll
        for (int i = 0; i < VEC; i++) {
            float ns = fmaf(s[i], cd[i],  c[i] * sd[i]);
            float nc = fmaf(c[i], cd[i], -s[i] * sd[i]);
            s[i] = ns; c[i] = nc;
        }

        // odd row: add cos
        float4 o1;
        o1.x = v1.x + c[0];
        o1.y = v1.y + c[1];
        o1.z = v1.z + c[2];
        o1.w = v1.w + c[3];
        *reinterpret_cast<float4*>(outp + (size_t)(r + 1) * D) = o1;

        // rotate to row r+2
#pragma unroll
        for (int i = 0; i < VEC; i++) {
            float ns = fmaf(s[i], cd[i],  c[i] * sd[i]);
            float nc = fmaf(c[i], cd[i], -s[i] * sd[i]);
            s[i] = ns; c[i] = nc;
        }
    }
}

extern "C" void kernel_launch(void* const* d_in, const int* in_sizes, int n_in,
                              void* d_out, int out_size)
{
    const int*   ids = (const int*)d_in[0];
    const float* W   = (const float*)d_in[1];
    float*       out = (float*)d_out;

    const int rows = in_sizes[0];             // 8192 tokens
    emb_pe_kernel<<<rows / R, THREADS>>>(ids, W, out);
}

// round 3
// speedup vs baseline: 1.5970x; 1.2149x over previous
#include <cuda_runtime.h>
#include <cuda_bf16.h>
#include <cstdint>

// Embedding gather + sinusoidal positional encoding.
// out[row, c] = W[ids[row], c] + (row even ? sin : cos)(row * freq(c)),
//   freq(c) = 10000^(-2c/D)
//
// D = 1024, TOKENS = 8192.
// Block = 8 rows x 1024 cols. Thread t owns columns 4t..4t+3 for all 8 rows.
// All 8 gather loads are issued up front (MLP=8) to hide DRAM latency;
// PE via rotor recurrence (4 FMA / column / row) seeded by accurate sincosf.

static constexpr int D       = 1024;
static constexpr int VEC     = 4;
static constexpr int THREADS = D / VEC;   // 256
static constexpr int R       = 8;         // rows per block (even!)

__global__ __launch_bounds__(THREADS)
void emb_pe_kernel(const int* __restrict__ ids,
                   const float* __restrict__ W,
                   float* __restrict__ out)
{
    const int row0 = blockIdx.x * R;          // always even
    const int t    = threadIdx.x;             // 0..255
    const int c0   = t * VEC;                 // starting column

    __shared__ int sids[R];
    if (t < R) sids[t] = ids[row0 + t];
    __syncthreads();

    const float* Wc = W + c0;

    // Issue ALL row gathers up front — 8 independent LDG.128 in flight.
    float4 v[R];
#pragma unroll
    for (int r = 0; r < R; r++)
        v[r] = *reinterpret_cast<const float4*>(Wc + (size_t)sids[r] * D);

    // freq(c) = 2^(kexp * c),  kexp = -2*log2(10000)/D
    const float kexp = -13.287712379549449f * 2.0f / (float)D;
    const float pos0 = (float)row0;

    float s[VEC], c[VEC], sd[VEC], cd[VEC];
#pragma unroll
    for (int i = 0; i < VEC; i++) {
        float freq = exp2f(kexp * (float)(c0 + i));
        sincosf(pos0 * freq, &s[i], &c[i]);   // start rotor (accurate)
        sincosf(freq,        &sd[i], &cd[i]); // per-row delta rotor
    }

    float* outp = out + (size_t)row0 * D + c0;

#pragma unroll
    for (int r = 0; r < R; r += 2) {
        // even row: add sin
        float4 o0;
        o0.x = v[r].x + s[0];
        o0.y = v[r].y + s[1];
        o0.z = v[r].z + s[2];
        o0.w = v[r].w + s[3];
        *reinterpret_cast<float4*>(outp + (size_t)r * D) = o0;

        // rotate to row r+1
#pragma unroll
        for (int i = 0; i < VEC; i++) {
            float ns = fmaf(s[i], cd[i],  c[i] * sd[i]);
            float nc = fmaf(c[i], cd[i], -s[i] * sd[i]);
            s[i] = ns; c[i] = nc;
        }

        // odd row: add cos
        float4 o1;
        o1.x = v[r + 1].x + c[0];
        o1.y = v[r + 1].y + c[1];
        o1.z = v[r + 1].z + c[2];
        o1.w = v[r + 1].w + c[3];
        *reinterpret_cast<float4*>(outp + (size_t)(r + 1) * D) = o1;

        // rotate to row r+2
#pragma unroll
        for (int i = 0; i < VEC; i++) {
            float ns = fmaf(s[i], cd[i],  c[i] * sd[i]);
            float nc = fmaf(c[i], cd[i], -s[i] * sd[i]);
            s[i] = ns; c[i] = nc;
        }
    }
}

extern "C" void kernel_launch(void* const* d_in, const int* in_sizes, int n_in,
                              void* d_out, int out_size)
{
    const int*   ids = (const int*)d_in[0];
    const float* W   = (const float*)d_in[1];
    float*       out = (float*)d_out;

    const int rows = in_sizes[0];             // 8192 tokens
    emb_pe_kernel<<<rows / R, THREADS>>>(ids, W, out);
}